// round 13
// baseline (speedup 1.0000x reference)
#include <cuda_runtime.h>
#include <cuda_bf16.h>
#include <cstdint>

#define BB 8
#define NN 256
#define MM 16
#define DD 256

// scratch: bf16 centroids, bf16 embeddings (tile-1 rows only), batch flags
__device__ __align__(16) __nv_bfloat16 g_C[BB * NN * DD];
__device__ __align__(16) __nv_bfloat16 g_Ebf[BB * NN * MM * DD];
__device__ int g_flag[BB];

// ============================ helpers ============================
__device__ __forceinline__ uint32_t smem_u32(const void* p) {
    uint32_t a;
    asm("{ .reg .u64 t; cvta.to.shared.u64 t, %1; cvt.u32.u64 %0, t; }"
        : "=r"(a) : "l"(p));
    return a;
}
__device__ __forceinline__ float ex2f(float x) {
    float y; asm("ex2.approx.ftz.f32 %0, %1;" : "=f"(y) : "f"(x)); return y;
}
__device__ __forceinline__ float lg2f(float x) {
    float y; asm("lg2.approx.ftz.f32 %0, %1;" : "=f"(y) : "f"(x)); return y;
}
__device__ __forceinline__ void ldm_x4(uint32_t* r, uint32_t addr) {
    asm volatile("ldmatrix.sync.aligned.m8n8.x4.shared.b16 {%0,%1,%2,%3}, [%4];"
                 : "=r"(r[0]), "=r"(r[1]), "=r"(r[2]), "=r"(r[3])
                 : "r"(addr));
}
__device__ __forceinline__ void mma16816(float* d, const uint32_t* a,
                                         uint32_t b0, uint32_t b1) {
    asm volatile(
        "mma.sync.aligned.m16n8k16.row.col.f32.bf16.bf16.f32 "
        "{%0,%1,%2,%3}, {%4,%5,%6,%7}, {%8,%9}, {%0,%1,%2,%3};"
        : "+f"(d[0]), "+f"(d[1]), "+f"(d[2]), "+f"(d[3])
        : "r"(a[0]), "r"(a[1]), "r"(a[2]), "r"(a[3]), "r"(b0), "r"(b1));
}
__device__ __forceinline__ void cp_async16(uint32_t dst, const void* src) {
    asm volatile("cp.async.cg.shared.global [%0], [%1], 16;"
                 :: "r"(dst), "l"(src) : "memory");
}
__device__ __forceinline__ uint4 pack_bf16x8(float4 v0, float4 v1) {
    __nv_bfloat162 p0 = __floats2bfloat162_rn(v0.x, v0.y);
    __nv_bfloat162 p1 = __floats2bfloat162_rn(v0.z, v0.w);
    __nv_bfloat162 p2 = __floats2bfloat162_rn(v1.x, v1.y);
    __nv_bfloat162 p3 = __floats2bfloat162_rn(v1.z, v1.w);
    uint4 pk;
    pk.x = *(uint32_t*)&p0; pk.y = *(uint32_t*)&p1;
    pk.z = *(uint32_t*)&p2; pk.w = *(uint32_t*)&p3;
    return pk;
}

// ============================ Kernel 0: reset flags + out ============================
__global__ void zero_kernel(float* __restrict__ out) {
    if (threadIdx.x < BB) g_flag[threadIdx.x] = 0;
    if (threadIdx.x == 0) out[0] = 0.f;
}

// ============================ Kernel 1: fused centroid + GEMM + LSE ==================
static constexpr int SQN0_OFF = 0;        // 128 floats
static constexpr int SQN1_OFF = 512;      // 128 floats
static constexpr int MSB_OFF  = 1024;     // float2[128][4] = 4096 B
static constexpr int SELF_OFF = 5120;     // 128 floats
static constexpr int RED_OFF  = 5632;     // 4 floats
static constexpr int A_OFF    = 8192;     // 128 rows x 512 B = 65536
static constexpr int B_OFF    = 73728;    // 256 rows x 512 B = 131072 (phase1: ssq 32KB)
static constexpr int SMEM_TOTAL = 204800;

#define SWZ(row, un) ((uint32_t)(row) * 512u + ((((uint32_t)(un)) ^ ((uint32_t)(row) & 7u)) << 4))

__global__ void __launch_bounds__(512, 1) loss_kernel(
    const float* __restrict__ E,
    const float* __restrict__ wp,
    const float* __restrict__ bp,
    float* __restrict__ out)
{
    extern __shared__ char smem[];
    uint32_t sb = smem_u32(smem);
    int tid = threadIdx.x, wid = tid >> 5, L = tid & 31;
    int warpM = wid & 3, warpN = wid >> 2;   // phase-2 warp grid 4x4, warp tile 32x64

    int bx    = blockIdx.x;        // 128 CTAs, all resident
    int batch = bx >> 4;
    int rt16  = bx & 15;           // 256-row block; rows n = rt16*16 .. rt16*16+15
    int rtb   = rt16 * 2;

    float w_s = *wp;
    float b_s = *bp;
    float*  sqn0 = (float*)(smem + SQN0_OFF);
    float*  sqn1 = (float*)(smem + SQN1_OFF);
    float2* msb  = (float2*)(smem + MSB_OFF);
    float*  SELF = (float*)(smem + SELF_OFF);
    float*  red  = (float*)(smem + RED_OFF);
    float*  ssq  = (float*)(smem + B_OFF);   // [256 rows][32 lanes], transient

    // ================= phase 1: read E fp32, centroids + bf16 + sq =================
    {
        int g = wid;                                    // group 0..15 (n = rt16*16+g)
        int rowbase = batch * 4096 + rt16 * 256 + g * 16;
        const float4* Ep = (const float4*)E + (size_t)rowbase * 64 + 2 * L;
        float4 c0 = make_float4(0.f, 0.f, 0.f, 0.f);
        float4 c1 = make_float4(0.f, 0.f, 0.f, 0.f);
#pragma unroll
        for (int m = 0; m < MM; m++) {
            float4 v0 = Ep[(size_t)m * 64];
            float4 v1 = Ep[(size_t)m * 64 + 1];
            c0.x += v0.x; c0.y += v0.y; c0.z += v0.z; c0.w += v0.w;
            c1.x += v1.x; c1.y += v1.y; c1.z += v1.z; c1.w += v1.w;
            ssq[(g * 16 + m) * 32 + L] =
                v0.x*v0.x + v0.y*v0.y + v0.z*v0.z + v0.w*v0.w +
                v1.x*v1.x + v1.y*v1.y + v1.z*v1.z + v1.w*v1.w;
            uint4 pk = pack_bf16x8(v0, v1);
            if (g < 8) {
                *(uint4*)(smem + A_OFF + SWZ(g * 16 + m, L)) = pk;   // tile 0 direct
            } else {
                *(uint4*)(g_Ebf + (size_t)(rowbase + m) * DD + L * 8) = pk;  // tile 1
            }
        }
        const float inv = 1.0f / MM;
        c0.x *= inv; c0.y *= inv; c0.z *= inv; c0.w *= inv;
        c1.x *= inv; c1.y *= inv; c1.z *= inv; c1.w *= inv;
        uint4 cp = pack_bf16x8(c0, c1);
        *(uint4*)(g_C + (size_t)(batch * NN + rt16 * 16 + g) * DD + L * 8) = cp;
    }
    __syncthreads();

    // reduce ssq -> sqn0/sqn1 (thread pair per row; float4 reads, conflict-free)
    {
        int r = tid >> 1, h = tid & 1;
        const float4* sp = (const float4*)ssq + (size_t)tid * 4;
        float4 a0 = sp[0], a1 = sp[1], a2 = sp[2], a3 = sp[3];
        float a = a0.x+a0.y+a0.z+a0.w + a1.x+a1.y+a1.z+a1.w
                + a2.x+a2.y+a2.z+a2.w + a3.x+a3.y+a3.z+a3.w;
        a += __shfl_xor_sync(0xFFFFFFFFu, a, 1);
        if (h == 0) {
            if (r < 128) sqn0[r] = a;
            else         sqn1[r - 128] = a;
        }
    }
    __threadfence();
    __syncthreads();

    // ---- cross-CTA batch sync: all 16 CTAs' centroids in L2 ----
    if (tid == 0) {
        atomicAdd(&g_flag[batch], 1);
        int v;
        do {
            asm volatile("ld.volatile.global.s32 %0, [%1];"
                         : "=r"(v) : "l"(g_flag + batch));
            if (v >= 16) break;
            __nanosleep(64);
        } while (true);
    }
    __syncthreads();

    // ---- B tile via cp.async: C[batch] [256 x 256] bf16 (overwrites ssq area) ----
    {
        const char* Cg = (const char*)(g_C + (size_t)batch * NN * DD);
#pragma unroll
        for (int it = 0; it < 16; it++) {
            int u = it * 512 + tid;
            cp_async16(sb + B_OFF + SWZ(u >> 5, u & 31), Cg + (size_t)u * 16);
        }
        asm volatile("cp.async.commit_group;" ::: "memory");
        asm volatile("cp.async.wait_group 0;" ::: "memory");
    }
    __syncthreads();

    // ================= phase 2: proven R12 GEMM + fused LSE =================
    uint32_t arsk = (uint32_t)((L >> 4) ^ (L & 7));
    uint32_t aB0  = sb + A_OFF + (uint32_t)(warpM * 32 + (L & 15)) * 512u;
    uint32_t aB1  = aB0 + 16 * 512;
    uint32_t brsk = (uint32_t)(((L >> 3) & 1) ^ (L & 7));
    uint32_t bB[4];
#pragma unroll
    for (int nb = 0; nb < 4; nb++)
        bB[nb] = sb + B_OFF +
                 (uint32_t)(warpN * 64 + nb * 16 + ((L >> 4) << 3) + (L & 7)) * 512u;

    const float L2E = 1.44269504f, LN2 = 0.69314718f;
    float wdiv = w_s * (1.0f / 15.0f);
    float total = 0.f;

    for (int t2 = 0; t2 < 2; t2++) {
        int rt = rtb + t2;
        float* sqn = t2 ? sqn1 : sqn0;

        float acc[2][8][4];
#pragma unroll
        for (int f = 0; f < 2; f++)
#pragma unroll
            for (int j = 0; j < 8; j++)
#pragma unroll
                for (int u = 0; u < 4; u++) acc[f][j][u] = 0.f;

#pragma unroll 4
        for (int ks = 0; ks < 16; ks++) {
            uint32_t ku = (uint32_t)(ks * 2);
            uint32_t xa = ((ku ^ arsk) << 4);
            uint32_t xb = ((ku ^ brsk) << 4);
            uint32_t a0[4], a1[4];
            ldm_x4(a0, aB0 + xa);
            ldm_x4(a1, aB1 + xa);
#pragma unroll
            for (int nb = 0; nb < 4; nb++) {
                uint32_t bf[4];
                ldm_x4(bf, bB[nb] + xb);
                mma16816(acc[0][2 * nb],     a0, bf[0], bf[1]);
                mma16816(acc[0][2 * nb + 1], a0, bf[2], bf[3]);
                mma16816(acc[1][2 * nb],     a1, bf[0], bf[1]);
                mma16816(acc[1][2 * nb + 1], a1, bf[2], bf[3]);
            }
        }
        __syncthreads();   // all warps done reading A smem

        // prefetch tile-1 A (written by this CTA in phase 1) under the epilogue
        if (t2 == 0) {
            const char* Ag = (const char*)(g_Ebf +
                ((size_t)(batch * 4096 + rt16 * 256 + 128)) * DD);
#pragma unroll
            for (int it = 0; it < 8; it++) {
                int u = it * 512 + tid;
                cp_async16(sb + A_OFF + SWZ(u >> 5, u & 31), Ag + (size_t)u * 16);
            }
            asm volatile("cp.async.commit_group;" ::: "memory");
        }

        // epilogue: in-place xv; direct diagonal SELF write; per-warp partial LSE
#pragma unroll
        for (int f = 0; f < 2; f++) {
            int dk = rt * 8 + warpM * 2 + f;
#pragma unroll
            for (int rh = 0; rh < 2; rh++) {
                int row = warpM * 32 + f * 16 + rh * 8 + (L >> 2);
                float sq = sqn[row];
                float m = -1e30f;
#pragma unroll
                for (int j = 0; j < 8; j++) {
#pragma unroll
                    for (int cq = 0; cq < 2; cq++) {
                        float v = acc[f][j][rh * 2 + cq];
                        int col = warpN * 64 + (j >> 1) * 16 + (j & 1) * 8 + (L & 3) * 2 + cq;
                        bool dg = (col == dk);
                        float xv = dg ? fmaf(wdiv, fmaf(16.f, v, -sq), b_s)
                                      : fmaf(w_s, v, b_s);
                        if (dg) SELF[row] = xv;
                        acc[f][j][rh * 2 + cq] = xv;
                        m = fmaxf(m, xv);
                    }
                }
                m = fmaxf(m, __shfl_xor_sync(0xFFFFFFFFu, m, 1));
                m = fmaxf(m, __shfl_xor_sync(0xFFFFFFFFu, m, 2));
                float s = 0.f;
#pragma unroll
                for (int j = 0; j < 8; j++) {
#pragma unroll
                    for (int cq = 0; cq < 2; cq++)
                        s += ex2f((acc[f][j][rh * 2 + cq] - m) * L2E);
                }
                s += __shfl_xor_sync(0xFFFFFFFFu, s, 1);
                s += __shfl_xor_sync(0xFFFFFFFFu, s, 2);
                if ((L & 3) == 0) msb[row * 4 + warpN] = make_float2(m, s);
            }
        }
        __syncthreads();

        if (tid < 128) {
            float2 p0 = msb[tid * 4 + 0], p1 = msb[tid * 4 + 1];
            float2 p2 = msb[tid * 4 + 2], p3 = msb[tid * 4 + 3];
            float m = fmaxf(fmaxf(p0.x, p1.x), fmaxf(p2.x, p3.x));
            float s = p0.y * ex2f((p0.x - m) * L2E) + p1.y * ex2f((p1.x - m) * L2E)
                    + p2.y * ex2f((p2.x - m) * L2E) + p3.y * ex2f((p3.x - m) * L2E);
            float contrib = m + lg2f(s) * LN2 - SELF[tid];
            contrib += __shfl_xor_sync(0xFFFFFFFFu, contrib, 16);
            contrib += __shfl_xor_sync(0xFFFFFFFFu, contrib, 8);
            contrib += __shfl_xor_sync(0xFFFFFFFFu, contrib, 4);
            contrib += __shfl_xor_sync(0xFFFFFFFFu, contrib, 2);
            contrib += __shfl_xor_sync(0xFFFFFFFFu, contrib, 1);
            if (L == 0) red[wid] = contrib;
        }
        __syncthreads();
        if (tid == 0) total += red[0] + red[1] + red[2] + red[3];
        if (t2 == 0) { asm volatile("cp.async.wait_group 0;" ::: "memory"); }
        __syncthreads();
    }

    if (tid == 0) atomicAdd(out, total);
}

// ============================ launch ============================
extern "C" void kernel_launch(void* const* d_in, const int* in_sizes, int n_in,
                              void* d_out, int out_size) {
    const float* E  = (const float*)d_in[0];
    const float* wp = (const float*)d_in[1];
    const float* bp = (const float*)d_in[2];
    float* out = (float*)d_out;

    zero_kernel<<<1, 32>>>(out);

    cudaFuncSetAttribute(loss_kernel, cudaFuncAttributeMaxDynamicSharedMemorySize, SMEM_TOTAL);
    loss_kernel<<<128, 512, SMEM_TOTAL>>>(E, wp, bp, out);
}

// round 14
// speedup vs baseline: 1.1892x; 1.1892x over previous
#include <cuda_runtime.h>
#include <cuda_bf16.h>
#include <cstdint>

#define BB 8
#define NN 256
#define MM 16
#define DD 256

// scratch: bf16 centroids, bf16 embeddings, fp32 row sq_norms
__device__ __align__(16) __nv_bfloat16 g_C[BB * NN * DD];
__device__ __align__(16) __nv_bfloat16 g_Ebf[BB * NN * MM * DD];
__device__ float g_SQN[BB * NN * MM];

// ============================ helpers ============================
__device__ __forceinline__ uint32_t smem_u32(const void* p) {
    uint32_t a;
    asm("{ .reg .u64 t; cvta.to.shared.u64 t, %1; cvt.u32.u64 %0, t; }"
        : "=r"(a) : "l"(p));
    return a;
}
__device__ __forceinline__ float ex2f(float x) {
    float y; asm("ex2.approx.ftz.f32 %0, %1;" : "=f"(y) : "f"(x)); return y;
}
__device__ __forceinline__ float lg2f(float x) {
    float y; asm("lg2.approx.ftz.f32 %0, %1;" : "=f"(y) : "f"(x)); return y;
}
__device__ __forceinline__ void ldm_x4(uint32_t* r, uint32_t addr) {
    asm volatile("ldmatrix.sync.aligned.m8n8.x4.shared.b16 {%0,%1,%2,%3}, [%4];"
                 : "=r"(r[0]), "=r"(r[1]), "=r"(r[2]), "=r"(r[3])
                 : "r"(addr));
}
__device__ __forceinline__ void mma16816(float* d, const uint32_t* a,
                                         uint32_t b0, uint32_t b1) {
    asm volatile(
        "mma.sync.aligned.m16n8k16.row.col.f32.bf16.bf16.f32 "
        "{%0,%1,%2,%3}, {%4,%5,%6,%7}, {%8,%9}, {%0,%1,%2,%3};"
        : "+f"(d[0]), "+f"(d[1]), "+f"(d[2]), "+f"(d[3])
        : "r"(a[0]), "r"(a[1]), "r"(a[2]), "r"(a[3]), "r"(b0), "r"(b1));
}
__device__ __forceinline__ void cp_async16(uint32_t dst, const void* src) {
    asm volatile("cp.async.cg.shared.global [%0], [%1], 16;"
                 :: "r"(dst), "l"(src) : "memory");
}
__device__ __forceinline__ void bar_sync(int id) {
    asm volatile("bar.sync %0, 512;" :: "r"(id) : "memory");
}
__device__ __forceinline__ void bar_arrive(int id) {
    asm volatile("bar.arrive %0, 512;" :: "r"(id) : "memory");
}
__device__ __forceinline__ void gbar(int g) {
    asm volatile("bar.sync %0, 256;" :: "r"(4 + g) : "memory");
}

// ============================ Kernel 1: centroids + bf16 E + sq_norms (R12) ============
__global__ void centroid_kernel(const float* __restrict__ E, float* __restrict__ out) {
    __shared__ float ssq[4][16][68];
    int tid = threadIdx.x;
    int idx = blockIdx.x * 256 + tid;
    if (idx == 0) out[0] = 0.f;
    int d4 = idx & 63, bn = idx >> 6;
    int g  = tid >> 6;
    const float4* p = (const float4*)E + (size_t)bn * MM * 64 + d4;
    float4 s = make_float4(0.f, 0.f, 0.f, 0.f);
#pragma unroll
    for (int m = 0; m < MM; m++) {
        float4 v = p[m * 64];
        s.x += v.x; s.y += v.y; s.z += v.z; s.w += v.w;
        ssq[g][m][d4] = v.x*v.x + v.y*v.y + v.z*v.z + v.w*v.w;
        __nv_bfloat162 lo = __floats2bfloat162_rn(v.x, v.y);
        __nv_bfloat162 hi = __floats2bfloat162_rn(v.z, v.w);
        uint2 pk; pk.x = *(uint32_t*)&lo; pk.y = *(uint32_t*)&hi;
        *(uint2*)(g_Ebf + ((size_t)bn * MM + m) * DD + d4 * 4) = pk;
    }
    const float inv = 1.0f / MM;
    __nv_bfloat162 lo = __floats2bfloat162_rn(s.x * inv, s.y * inv);
    __nv_bfloat162 hi = __floats2bfloat162_rn(s.z * inv, s.w * inv);
    uint2 pk; pk.x = *(uint32_t*)&lo; pk.y = *(uint32_t*)&hi;
    *(uint2*)(g_C + (size_t)bn * DD + d4 * 4) = pk;

    __syncthreads();
    int lr = tid >> 2, q = tid & 3;
    float acc = 0.f;
#pragma unroll
    for (int k = 0; k < 16; k++) acc += ssq[lr >> 4][lr & 15][q * 16 + k];
    acc += __shfl_xor_sync(0xFFFFFFFFu, acc, 1);
    acc += __shfl_xor_sync(0xFFFFFFFFu, acc, 2);
    if (q == 0) g_SQN[blockIdx.x * 64 + lr] = acc;
}

// ============================ Kernel 2: ping-pong GEMM + fused LSE ==================
// Grid 128. CTA = 4 subtiles of 64 rows x 256 cols. Group g owns subtiles {g, g+2}.
// MMA token (named bars 1..3) forces MMA(s) || EPI(s-1) overlap.
static constexpr int SQN_OFF  = 0;        // 256 floats = 1024 B
static constexpr int MSB_OFF  = 1024;     // 2 groups x float2[64][4] = 4096 B
static constexpr int SELF_OFF = 5120;     // 2 x 64 floats = 512 B
static constexpr int RED_OFF  = 5632;     // 4 floats
static constexpr int A_OFF    = 8192;     // 2 groups x 32768 (64 rows x 512 B)
static constexpr int B_OFF    = 73728;    // 256 rows x 512 B = 131072
static constexpr int SMEM_TOTAL = 204800;

#define SWZ(row, un) ((uint32_t)(row) * 512u + ((((uint32_t)(un)) ^ ((uint32_t)(row) & 7u)) << 4))

__global__ void __launch_bounds__(512, 1) loss_kernel(
    const float* __restrict__ wp,
    const float* __restrict__ bp,
    float* __restrict__ out)
{
    extern __shared__ char smem[];
    uint32_t sb = smem_u32(smem);
    int tid = threadIdx.x, wid = tid >> 5, L = tid & 31;
    int g    = wid >> 3;           // group 0/1
    int gwid = wid & 7;
    int tig  = tid & 255;
    int warpM = gwid & 1, warpN = gwid >> 1;   // 2x4 grid, warp tile 32x64

    int bx    = blockIdx.x;
    int batch = bx >> 4;
    int rt16  = bx & 15;           // 256-row block

    float w_s = *wp;
    float b_s = *bp;
    float*  sqn  = (float*)(smem + SQN_OFF);
    float2* msb  = (float2*)(smem + MSB_OFF) + g * 256;
    float*  SELF = (float*)(smem + SELF_OFF) + g * 64;
    float*  red  = (float*)(smem + RED_OFF);

    uint32_t a_base = sb + A_OFF + (uint32_t)g * 32768u;
    const char* Ebase = (const char*)g_Ebf + (size_t)(batch * 4096 + rt16 * 256) * 512;

    // ---- prologue: B (all threads) + A subtile g (per group) + sqn ----
    {
        const char* Cg = (const char*)(g_C + (size_t)batch * NN * DD);
#pragma unroll
        for (int it = 0; it < 16; it++) {
            int u = it * 512 + tid;
            cp_async16(sb + B_OFF + SWZ(u >> 5, u & 31), Cg + (size_t)u * 16);
        }
        const char* Ag = Ebase + (size_t)g * 64 * 512;
#pragma unroll
        for (int it = 0; it < 8; it++) {
            int u = it * 256 + tig;
            cp_async16(a_base + SWZ(u >> 5, u & 31), Ag + (size_t)u * 16);
        }
        asm volatile("cp.async.commit_group;" ::: "memory");
        if (tid < 256) sqn[tid] = g_SQN[batch * 4096 + rt16 * 256 + tid];
        asm volatile("cp.async.wait_group 0;" ::: "memory");
    }
    __syncthreads();

    // ---- invariant addressing ----
    uint32_t arsk = (uint32_t)((L >> 4) ^ (L & 7));
    uint32_t aB0  = a_base + (uint32_t)(warpM * 32 + (L & 15)) * 512u;
    uint32_t aB1  = aB0 + 16 * 512;
    uint32_t brsk = (uint32_t)(((L >> 3) & 1) ^ (L & 7));
    uint32_t bB[4];
#pragma unroll
    for (int nb = 0; nb < 4; nb++)
        bB[nb] = sb + B_OFF +
                 (uint32_t)(warpN * 64 + nb * 16 + ((L >> 4) << 3) + (L & 7)) * 512u;

    const float L2E = 1.44269504f, LN2 = 0.69314718f;
    float wdiv = w_s * (1.0f / 15.0f);

    for (int t2 = 0; t2 < 2; t2++) {
        int s = t2 * 2 + g;            // subtile index 0..3

        // token: wait until MMA of subtile s-1 is done
        if (s > 0) bar_sync(s);

        float acc[2][8][4];
#pragma unroll
        for (int f = 0; f < 2; f++)
#pragma unroll
            for (int j = 0; j < 8; j++)
#pragma unroll
                for (int u = 0; u < 4; u++) acc[f][j][u] = 0.f;

#pragma unroll 4
        for (int ks = 0; ks < 16; ks++) {
            uint32_t ku = (uint32_t)(ks * 2);
            uint32_t xa = ((ku ^ arsk) << 4);
            uint32_t xb = ((ku ^ brsk) << 4);
            uint32_t a0[4], a1[4];
            ldm_x4(a0, aB0 + xa);
            ldm_x4(a1, aB1 + xa);
#pragma unroll
            for (int nb = 0; nb < 4; nb++) {
                uint32_t bf[4];
                ldm_x4(bf, bB[nb] + xb);
                mma16816(acc[0][2 * nb],     a0, bf[0], bf[1]);
                mma16816(acc[0][2 * nb + 1], a0, bf[2], bf[3]);
                mma16816(acc[1][2 * nb],     a1, bf[0], bf[1]);
                mma16816(acc[1][2 * nb + 1], a1, bf[2], bf[3]);
            }
        }
        if (s < 3) bar_arrive(s + 1);   // pass MMA token to the other group
        gbar(g);                        // group done reading its A buffer

        // refill own A buffer with subtile s+2 (hidden under epilogue)
        if (t2 == 0) {
            const char* Ag = Ebase + (size_t)(s + 2) * 64 * 512;
#pragma unroll
            for (int it = 0; it < 8; it++) {
                int u = it * 256 + tig;
                cp_async16(a_base + SWZ(u >> 5, u & 31), Ag + (size_t)u * 16);
            }
            asm volatile("cp.async.commit_group;" ::: "memory");
        }

        // ---- epilogue: in-place xv; direct SELF; per-warp partial LSE ----
#pragma unroll
        for (int f = 0; f < 2; f++) {
            int dk = rt16 * 16 + s * 4 + warpM * 2 + f;
#pragma unroll
            for (int rh = 0; rh < 2; rh++) {
                int row = warpM * 32 + f * 16 + rh * 8 + (L >> 2);   // [0,64)
                float sq = sqn[s * 64 + row];
                float m = -1e30f;
#pragma unroll
                for (int j = 0; j < 8; j++) {
#pragma unroll
                    for (int cq = 0; cq < 2; cq++) {
                        float v = acc[f][j][rh * 2 + cq];
                        int col = warpN * 64 + (j >> 1) * 16 + (j & 1) * 8 + (L & 3) * 2 + cq;
                        bool dg = (col == dk);
                        float xv = dg ? fmaf(wdiv, fmaf(16.f, v, -sq), b_s)
                                      : fmaf(w_s, v, b_s);
                        if (dg) SELF[row] = xv;
                        acc[f][j][rh * 2 + cq] = xv;
                        m = fmaxf(m, xv);
                    }
                }
                m = fmaxf(m, __shfl_xor_sync(0xFFFFFFFFu, m, 1));
                m = fmaxf(m, __shfl_xor_sync(0xFFFFFFFFu, m, 2));
                float sm = 0.f;
#pragma unroll
                for (int j = 0; j < 8; j++) {
#pragma unroll
                    for (int cq = 0; cq < 2; cq++)
                        sm += ex2f((acc[f][j][rh * 2 + cq] - m) * L2E);
                }
                sm += __shfl_xor_sync(0xFFFFFFFFu, sm, 1);
                sm += __shfl_xor_sync(0xFFFFFFFFu, sm, 2);
                if ((L & 3) == 0) msb[row * 4 + warpN] = make_float2(m, sm);
            }
        }
        gbar(g);   // msb/SELF written

        // ---- merge 4 warpN partials per row (tig<64) ----
        if (tig < 64) {
            float2 p0 = msb[tig * 4 + 0], p1 = msb[tig * 4 + 1];
            float2 p2 = msb[tig * 4 + 2], p3 = msb[tig * 4 + 3];
            float m = fmaxf(fmaxf(p0.x, p1.x), fmaxf(p2.x, p3.x));
            float sm = p0.y * ex2f((p0.x - m) * L2E) + p1.y * ex2f((p1.x - m) * L2E)
                     + p2.y * ex2f((p2.x - m) * L2E) + p3.y * ex2f((p3.x - m) * L2E);
            float contrib = m + lg2f(sm) * LN2 - SELF[tig];
            contrib += __shfl_xor_sync(0xFFFFFFFFu, contrib, 16);
            contrib += __shfl_xor_sync(0xFFFFFFFFu, contrib, 8);
            contrib += __shfl_xor_sync(0xFFFFFFFFu, contrib, 4);
            contrib += __shfl_xor_sync(0xFFFFFFFFu, contrib, 2);
            contrib += __shfl_xor_sync(0xFFFFFFFFu, contrib, 1);
            if (L == 0) {
                int slot = g * 2 + (tig >> 5);
                if (t2 == 0) red[slot] = contrib;
                else         red[slot] += contrib;
            }
        }
        if (t2 == 0) { asm volatile("cp.async.wait_group 0;" ::: "memory"); }
        gbar(g);   // msb free for next subtile; A(s+2) fully landed
    }

    if (tig == 0) atomicAdd(out, red[g * 2] + red[g * 2 + 1]);
}

// ============================ launch ============================
extern "C" void kernel_launch(void* const* d_in, const int* in_sizes, int n_in,
                              void* d_out, int out_size) {
    const float* E  = (const float*)d_in[0];
    const float* wp = (const float*)d_in[1];
    const float* bp = (const float*)d_in[2];
    float* out = (float*)d_out;

    centroid_kernel<<<BB * NN / 4, 256>>>(E, out);

    cudaFuncSetAttribute(loss_kernel, cudaFuncAttributeMaxDynamicSharedMemorySize, SMEM_TOTAL);
    loss_kernel<<<128, 512, SMEM_TOTAL>>>(wp, bp, out);
}